// round 1
// baseline (speedup 1.0000x reference)
#include <cuda_runtime.h>
#include <cuda_bf16.h>

#define TICKS 10000
#define S_BINS 9
#define OUT_CH 64

// Scratch: 9x10000 classification histogram and 9x10000 suffix-summed buffer.
__device__ __align__(16) float g_G[S_BINS * TICKS];
__device__ __align__(16) float g_BUF[S_BINS * TICKS];

// ---------------------------------------------------------------------------
// K1: zero both scratch buffers (180000 floats)
// ---------------------------------------------------------------------------
__global__ void k_zero() {
    int idx = blockIdx.x * blockDim.x + threadIdx.x;
    if (idx < S_BINS * TICKS) {
        g_G[idx]   = 0.0f;
        g_BUF[idx] = 0.0f;
    }
}

// ---------------------------------------------------------------------------
// K2: event scatter.
//   stride==1 fast path: 1 atomicAdd per event into G[min(y,2)*3+min(x,2)][t]
//   fallback: 9 validity-checked atomicAdds into BUF directly
// Each thread processes 4 events via vectorized loads.
// ---------------------------------------------------------------------------
__global__ void k_scatter(const float* __restrict__ vals,
                          const int*   __restrict__ ticks,
                          const int*   __restrict__ xs,
                          const int*   __restrict__ ys,
                          const int*   __restrict__ stride_p,
                          int n) {
    const int st = *stride_p;   // uniform
    const int tid = blockIdx.x * blockDim.x + threadIdx.x;
    const int base = tid * 4;

    if (base + 3 < n) {
        float4 v4 = *reinterpret_cast<const float4*>(vals  + base);
        int4   t4 = *reinterpret_cast<const int4*>  (ticks + base);
        int4   x4 = *reinterpret_cast<const int4*>  (xs    + base);
        int4   y4 = *reinterpret_cast<const int4*>  (ys    + base);

        float v[4] = {v4.x, v4.y, v4.z, v4.w};
        int   t[4] = {t4.x, t4.y, t4.z, t4.w};
        int   x[4] = {x4.x, x4.y, x4.z, x4.w};
        int   y[4] = {y4.x, y4.y, y4.z, y4.w};

        if (st == 1) {
            #pragma unroll
            for (int i = 0; i < 4; i++) {
                int cx = x[i] < 2 ? x[i] : 2;
                int cy = y[i] < 2 ? y[i] : 2;
                atomicAdd(&g_G[(cy * 3 + cx) * TICKS + t[i]], v[i]);
            }
        } else {
            #pragma unroll
            for (int i = 0; i < 4; i++) {
                #pragma unroll
                for (int ky = 0; ky < 3; ky++) {
                    #pragma unroll
                    for (int kx = 0; kx < 3; kx++) {
                        int ox = x[i] - kx;
                        int oy = y[i] - ky;
                        if (ox >= 0 && oy >= 0 && (ox % st) == 0 && (oy % st) == 0) {
                            atomicAdd(&g_BUF[(ky * 3 + kx) * TICKS + t[i]], v[i]);
                        }
                    }
                }
            }
        }
    } else if (base < n) {
        // scalar tail
        for (int i = base; i < n; i++) {
            float v = vals[i];
            int   t = ticks[i];
            int   x = xs[i];
            int   y = ys[i];
            if (st == 1) {
                int cx = x < 2 ? x : 2;
                int cy = y < 2 ? y : 2;
                atomicAdd(&g_G[(cy * 3 + cx) * TICKS + t], v);
            } else {
                for (int ky = 0; ky < 3; ky++)
                    for (int kx = 0; kx < 3; kx++) {
                        int ox = x - kx, oy = y - ky;
                        if (ox >= 0 && oy >= 0 && (ox % st) == 0 && (oy % st) == 0)
                            atomicAdd(&g_BUF[(ky * 3 + kx) * TICKS + t], v);
                    }
            }
        }
    }
}

// ---------------------------------------------------------------------------
// K3: 3x3 2D suffix sum over bins: BUF[ky*3+kx][t] = sum_{cy>=ky, cx>=kx} G[cy*3+cx][t]
// Only meaningful on the stride==1 fast path; no-op otherwise (BUF already final).
// ---------------------------------------------------------------------------
__global__ void k_suffix(const int* __restrict__ stride_p) {
    if (*stride_p != 1) return;
    int t = blockIdx.x * blockDim.x + threadIdx.x;
    if (t >= TICKS) return;

    float g[9];
    #pragma unroll
    for (int b = 0; b < 9; b++) g[b] = g_G[b * TICKS + t];

    // suffix over cx within each cy row
    #pragma unroll
    for (int cy = 0; cy < 3; cy++) {
        g[cy * 3 + 1] += g[cy * 3 + 2];
        g[cy * 3 + 0] += g[cy * 3 + 1];
    }
    // suffix over cy within each kx column
    #pragma unroll
    for (int kx = 0; kx < 3; kx++) {
        g[1 * 3 + kx] += g[2 * 3 + kx];
        g[0 * 3 + kx] += g[1 * 3 + kx];
    }

    #pragma unroll
    for (int b = 0; b < 9; b++) g_BUF[b * TICKS + t] = g[b];
}

// ---------------------------------------------------------------------------
// K4: broadcast BUF[9][T] to out[64][9][T], float4-vectorized.
// T = 10000 -> 2500 float4 per (c,s) row; BUF stays L2-resident (360 KB).
// ---------------------------------------------------------------------------
#define T4 (TICKS / 4)   // 2500

__global__ void k_broadcast(float4* __restrict__ out) {
    int v = blockIdx.x * blockDim.x + threadIdx.x;           // 0 .. 64*9*2500-1
    if (v >= OUT_CH * S_BINS * T4) return;
    int row = v / T4;                                        // c*9 + s
    int col = v - row * T4;
    int s   = row % S_BINS;
    const float4* buf4 = reinterpret_cast<const float4*>(g_BUF);
    out[v] = buf4[s * T4 + col];
}

// ---------------------------------------------------------------------------
extern "C" void kernel_launch(void* const* d_in, const int* in_sizes, int n_in,
                              void* d_out, int out_size) {
    const float* vals    = (const float*)d_in[0];
    const int*   ticks   = (const int*)  d_in[1];
    const int*   xs      = (const int*)  d_in[2];
    const int*   ys      = (const int*)  d_in[3];
    const int*   stridep = (const int*)  d_in[4];
    float* out = (float*)d_out;
    int n = in_sizes[0];

    // K1: zero scratch
    {
        int total = S_BINS * TICKS;
        k_zero<<<(total + 255) / 256, 256>>>();
    }
    // K2: scatter (4 events/thread)
    {
        int threads = (n + 3) / 4;
        k_scatter<<<(threads + 255) / 256, 256>>>(vals, ticks, xs, ys, stridep, n);
    }
    // K3: suffix sum
    k_suffix<<<(TICKS + 255) / 256, 256>>>(stridep);

    // K4: broadcast to all channels
    {
        int total4 = OUT_CH * S_BINS * T4;   // 1,440,000
        k_broadcast<<<(total4 + 255) / 256, 256>>>((float4*)out);
    }
}

// round 2
// speedup vs baseline: 2.1190x; 2.1190x over previous
#include <cuda_runtime.h>
#include <cuda_bf16.h>

#define TICKS 10000
#define S_BINS 9
#define OUT_CH 64
#define R_REP 16
#define PLANE (S_BINS * TICKS)      // 90000
#define T4 (TICKS / 4)              // 2500

// Replicated classification histograms + final suffix-summed buffer.
__device__ __align__(16) float g_GR[R_REP * PLANE];   // 5.76 MB
__device__ __align__(16) float g_BUF[PLANE];

// ---------------------------------------------------------------------------
// K1: zero scratch (float4-vectorized). PLANE and R_REP*PLANE divisible by 4.
// ---------------------------------------------------------------------------
__global__ void k_zero() {
    const int idx = blockIdx.x * blockDim.x + threadIdx.x;
    const int gr4 = (R_REP * PLANE) / 4;   // 360000
    const int b4  = PLANE / 4;             // 22500
    float4 z = make_float4(0.f, 0.f, 0.f, 0.f);
    if (idx < gr4) reinterpret_cast<float4*>(g_GR)[idx] = z;
    if (idx < b4)  reinterpret_cast<float4*>(g_BUF)[idx] = z;
}

// ---------------------------------------------------------------------------
// K2: event scatter with 16-way replica spreading.
//   stride==1: 1 atomicAdd/event into g_GR[r][bin][t], bin = min(y,2)*3+min(x,2)
//   fallback : 9 checked atomicAdds into g_BUF directly
// 4 events/thread via vectorized loads; replica = global warp id & 15.
// ---------------------------------------------------------------------------
__global__ void k_scatter(const float* __restrict__ vals,
                          const int*   __restrict__ ticks,
                          const int*   __restrict__ xs,
                          const int*   __restrict__ ys,
                          const int*   __restrict__ stride_p,
                          int n) {
    const int st  = *stride_p;
    const int tid = blockIdx.x * blockDim.x + threadIdx.x;
    const int rep = (tid >> 5) & (R_REP - 1);
    float* __restrict__ G = g_GR + rep * PLANE;
    const int base = tid * 4;

    if (base + 3 < n) {
        float4 v4 = *reinterpret_cast<const float4*>(vals  + base);
        int4   t4 = *reinterpret_cast<const int4*>  (ticks + base);
        int4   x4 = *reinterpret_cast<const int4*>  (xs    + base);
        int4   y4 = *reinterpret_cast<const int4*>  (ys    + base);

        float v[4] = {v4.x, v4.y, v4.z, v4.w};
        int   t[4] = {t4.x, t4.y, t4.z, t4.w};
        int   x[4] = {x4.x, x4.y, x4.z, x4.w};
        int   y[4] = {y4.x, y4.y, y4.z, y4.w};

        if (st == 1) {
            #pragma unroll
            for (int i = 0; i < 4; i++) {
                int cx = x[i] < 2 ? x[i] : 2;
                int cy = y[i] < 2 ? y[i] : 2;
                atomicAdd(&G[(cy * 3 + cx) * TICKS + t[i]], v[i]);
            }
        } else {
            #pragma unroll
            for (int i = 0; i < 4; i++) {
                #pragma unroll
                for (int ky = 0; ky < 3; ky++) {
                    #pragma unroll
                    for (int kx = 0; kx < 3; kx++) {
                        int ox = x[i] - kx, oy = y[i] - ky;
                        if (ox >= 0 && oy >= 0 && (ox % st) == 0 && (oy % st) == 0)
                            atomicAdd(&g_BUF[(ky * 3 + kx) * TICKS + t[i]], v[i]);
                    }
                }
            }
        }
    } else if (base < n) {
        for (int i = base; i < n; i++) {
            float v = vals[i];
            int   t = ticks[i], x = xs[i], y = ys[i];
            if (st == 1) {
                int cx = x < 2 ? x : 2;
                int cy = y < 2 ? y : 2;
                atomicAdd(&G[(cy * 3 + cx) * TICKS + t], v);
            } else {
                for (int ky = 0; ky < 3; ky++)
                    for (int kx = 0; kx < 3; kx++) {
                        int ox = x - kx, oy = y - ky;
                        if (ox >= 0 && oy >= 0 && (ox % st) == 0 && (oy % st) == 0)
                            atomicAdd(&g_BUF[(ky * 3 + kx) * TICKS + t], v);
                    }
            }
        }
    }
}

// ---------------------------------------------------------------------------
// K3: reduce 16 replicas + 3x3 2D suffix sum:
//   BUF[ky*3+kx][t] = sum_{cy>=ky, cx>=kx} sum_r GR[r][cy*3+cx][t]
// No-op for stride != 1 (BUF already holds the final answer).
// ---------------------------------------------------------------------------
__global__ void k_suffix(const int* __restrict__ stride_p) {
    if (*stride_p != 1) return;
    int t = blockIdx.x * blockDim.x + threadIdx.x;
    if (t >= TICKS) return;

    float g[9];
    #pragma unroll
    for (int b = 0; b < 9; b++) g[b] = 0.f;
    #pragma unroll
    for (int r = 0; r < R_REP; r++) {
        const float* G = g_GR + r * PLANE;
        #pragma unroll
        for (int b = 0; b < 9; b++) g[b] += G[b * TICKS + t];
    }

    // suffix over cx within each cy row
    #pragma unroll
    for (int cy = 0; cy < 3; cy++) {
        g[cy * 3 + 1] += g[cy * 3 + 2];
        g[cy * 3 + 0] += g[cy * 3 + 1];
    }
    // suffix over cy within each kx column
    #pragma unroll
    for (int kx = 0; kx < 3; kx++) {
        g[1 * 3 + kx] += g[2 * 3 + kx];
        g[0 * 3 + kx] += g[1 * 3 + kx];
    }

    #pragma unroll
    for (int b = 0; b < 9; b++) g_BUF[b * TICKS + t] = g[b];
}

// ---------------------------------------------------------------------------
// K4: broadcast BUF[9][T] to out[64][9][T].
// Each thread reads one float4 of BUF and stores it into all 64 channels.
// grid: (ceil(T4/256), S_BINS). Pure store-bound (~23MB).
// ---------------------------------------------------------------------------
__global__ void k_broadcast(float4* __restrict__ out) {
    int col = blockIdx.x * blockDim.x + threadIdx.x;   // 0..T4-1
    int s   = blockIdx.y;                               // 0..8
    if (col >= T4) return;
    float4 v = reinterpret_cast<const float4*>(g_BUF)[s * T4 + col];
    float4* dst = out + s * T4 + col;
    #pragma unroll
    for (int c = 0; c < OUT_CH; c++)
        dst[c * (S_BINS * T4)] = v;
}

// ---------------------------------------------------------------------------
extern "C" void kernel_launch(void* const* d_in, const int* in_sizes, int n_in,
                              void* d_out, int out_size) {
    const float* vals    = (const float*)d_in[0];
    const int*   ticks   = (const int*)  d_in[1];
    const int*   xs      = (const int*)  d_in[2];
    const int*   ys      = (const int*)  d_in[3];
    const int*   stridep = (const int*)  d_in[4];
    int n = in_sizes[0];

    // K1: zero scratch (360000 float4 max)
    {
        int total = (R_REP * PLANE) / 4;
        k_zero<<<(total + 255) / 256, 256>>>();
    }
    // K2: scatter, 4 events/thread
    {
        int threads = (n + 3) / 4;
        k_scatter<<<(threads + 255) / 256, 256>>>(vals, ticks, xs, ys, stridep, n);
    }
    // K3: replica-reduce + suffix sum
    k_suffix<<<(TICKS + 255) / 256, 256>>>(stridep);

    // K4: broadcast to all 64 channels
    {
        dim3 grid((T4 + 255) / 256, S_BINS);
        k_broadcast<<<grid, 256>>>((float4*)d_out);
    }
}